// round 1
// baseline (speedup 1.0000x reference)
#include <cuda_runtime.h>
#include <math.h>

#define NUM_USERS 100000
#define NUM_ITEMS 50000
#define N_NODES   150000
#define EMBED     128
#define N_EDGES   1000000
#define N_SYM     (2*N_EDGES)
#define HID       128
#define NUM_CAT   100
#define NUM_SKU   2000

// ---------------- static device scratch (no runtime allocation) ----------------
__device__ int   g_deg[N_NODES];
__device__ int   g_off[N_NODES + 1];
__device__ int   g_cur[N_NODES];
__device__ int   g_adj_col[N_SYM];
__device__ float g_adj_w[N_SYM];
__device__ float g_emb0[(size_t)N_NODES * EMBED];   // ping
__device__ float g_emb1[(size_t)N_NODES * EMBED];   // pong
__device__ float g_acc[(size_t)NUM_USERS * EMBED];  // layer-sum for user rows only
__device__ float g_h[(size_t)NUM_USERS * HID];      // MLP hidden scratch
__device__ int   g_bsum[256];

#define T_SCAN 1024

// ---------------- graph build ----------------
__global__ void k_zero() {
    int i = blockIdx.x * blockDim.x + threadIdx.x;
    if (i < N_NODES) { g_deg[i] = 0; g_cur[i] = 0; }
}

__global__ void k_deg(const int* __restrict__ ei) {
    int e = blockIdx.x * blockDim.x + threadIdx.x;
    if (e < N_EDGES) {
        atomicAdd(&g_deg[ei[e]], 1);             // forward edge, row = user
        atomicAdd(&g_deg[ei[N_EDGES + e]], 1);   // reversed edge, row = item
    }
}

// exclusive scan of g_deg -> g_off  (3 kernels: per-block scan, base scan, add)
__global__ void k_scan_part() {
    __shared__ int s[T_SCAN];
    int t = threadIdx.x, b = blockIdx.x;
    int i = b * T_SCAN + t;
    int v = (i < N_NODES) ? g_deg[i] : 0;
    s[t] = v;
    __syncthreads();
    for (int d = 1; d < T_SCAN; d <<= 1) {
        int x = (t >= d) ? s[t - d] : 0;
        __syncthreads();
        s[t] += x;
        __syncthreads();
    }
    if (i < N_NODES) g_off[i] = s[t] - v;   // exclusive within block
    if (t == T_SCAN - 1) g_bsum[b] = s[t];
}

__global__ void k_scan_base(int nb) {
    if (threadIdx.x == 0 && blockIdx.x == 0) {
        int run = 0;
        for (int b = 0; b < nb; b++) { int x = g_bsum[b]; g_bsum[b] = run; run += x; }
        g_off[N_NODES] = run;
    }
}

__global__ void k_scan_add() {
    int t = threadIdx.x, b = blockIdx.x;
    int i = b * T_SCAN + t;
    if (i < N_NODES) g_off[i] += g_bsum[b];
}

__global__ void k_fill(const int* __restrict__ ei) {
    int e = blockIdx.x * blockDim.x + threadIdx.x;
    if (e >= N_EDGES) return;
    int r = ei[e];
    int c = ei[N_EDGES + e];
    // both endpoints have deg >= 1 by construction
    float nrm = rsqrtf((float)g_deg[r]) * rsqrtf((float)g_deg[c]);
    int p = atomicAdd(&g_cur[r], 1);
    int ir = g_off[r] + p;
    g_adj_col[ir] = c; g_adj_w[ir] = nrm;
    int q = atomicAdd(&g_cur[c], 1);
    int ic = g_off[c] + q;
    g_adj_col[ic] = r; g_adj_w[ic] = nrm;
}

__global__ void k_embinit(const float* __restrict__ ue, const float* __restrict__ it) {
    size_t i = (size_t)blockIdx.x * blockDim.x + threadIdx.x;
    const size_t nu  = (size_t)NUM_USERS * EMBED;
    const size_t tot = (size_t)N_NODES * EMBED;
    if (i >= tot) return;
    float v = (i < nu) ? ue[i] : it[i - nu];
    g_emb0[i] = v;
    if (i < nu) g_acc[i] = v;
}

// ---------------- propagation: one block (128 thr) per destination row ----------------
__global__ void k_prop(int sel) {
    const float* __restrict__ src = sel ? g_emb1 : g_emb0;
    float* dst                    = sel ? g_emb0 : g_emb1;
    int row = blockIdx.x;
    int d   = threadIdx.x;
    int s   = g_off[row];
    int e2  = g_off[row + 1];
    float a = 0.f;
    int e = s;
    for (; e + 4 <= e2; e += 4) {
        int   c0 = g_adj_col[e],   c1 = g_adj_col[e+1], c2 = g_adj_col[e+2], c3 = g_adj_col[e+3];
        float w0 = g_adj_w[e],     w1 = g_adj_w[e+1],   w2 = g_adj_w[e+2],   w3 = g_adj_w[e+3];
        a = fmaf(w0, src[(size_t)c0 * EMBED + d], a);
        a = fmaf(w1, src[(size_t)c1 * EMBED + d], a);
        a = fmaf(w2, src[(size_t)c2 * EMBED + d], a);
        a = fmaf(w3, src[(size_t)c3 * EMBED + d], a);
    }
    for (; e < e2; e++)
        a = fmaf(g_adj_w[e], src[(size_t)g_adj_col[e] * EMBED + d], a);
    dst[(size_t)row * EMBED + d] = a;
    if (row < NUM_USERS) g_acc[(size_t)row * EMBED + d] += a;
}

__global__ void k_u(float* __restrict__ uo) {
    size_t i = (size_t)blockIdx.x * blockDim.x + threadIdx.x;
    if (i < (size_t)NUM_USERS * EMBED) uo[i] = g_acc[i] * 0.25f;
}

// ---------------- fused GEMM + bias + activation (K = 128 fixed) ----------------
// C[M,N] = act(A[M,128] @ B[128,N] + bias[N]).  64x64 tile, 4x4 per thread, K tiled by 64.
template <int ACT>   // 0 = relu, 1 = sigmoid
__global__ void __launch_bounds__(256) k_gemm(
    const float* __restrict__ A, const float* __restrict__ B,
    const float* __restrict__ bias, float* __restrict__ C,
    int M, int N)
{
    __shared__ float As[64][68];   // [k][m], +4 pad keeps float4 alignment & spreads banks
    __shared__ float Bs[64][68];   // [k][n]
    const int bm = blockIdx.y * 64;
    const int bn = blockIdx.x * 64;
    const int tid = threadIdx.x;
    const int tx = tid & 15, ty = tid >> 4;

    float acc[4][4] = {};

    for (int kt = 0; kt < 128; kt += 64) {
        // load A tile (64 rows x 64 k), transposed into As[k][m]
        #pragma unroll
        for (int i = tid; i < 64 * 64; i += 256) {
            int r = i >> 6, k = i & 63;
            float v = (bm + r < M) ? A[(size_t)(bm + r) * 128 + kt + k] : 0.f;
            As[k][r] = v;
        }
        // load B tile (64 k x 64 n)
        #pragma unroll
        for (int i = tid; i < 64 * 64; i += 256) {
            int k = i >> 6, n = i & 63;
            float v = (bn + n < N) ? B[(size_t)(kt + k) * N + bn + n] : 0.f;
            Bs[k][n] = v;
        }
        __syncthreads();

        #pragma unroll 8
        for (int k = 0; k < 64; k++) {
            float4 a4 = *(const float4*)&As[k][ty * 4];
            float4 b4 = *(const float4*)&Bs[k][tx * 4];
            float av[4] = {a4.x, a4.y, a4.z, a4.w};
            float bv[4] = {b4.x, b4.y, b4.z, b4.w};
            #pragma unroll
            for (int i2 = 0; i2 < 4; i2++)
                #pragma unroll
                for (int j = 0; j < 4; j++)
                    acc[i2][j] = fmaf(av[i2], bv[j], acc[i2][j]);
        }
        __syncthreads();
    }

    #pragma unroll
    for (int i2 = 0; i2 < 4; i2++) {
        int m = bm + ty * 4 + i2;
        if (m >= M) continue;
        #pragma unroll
        for (int j = 0; j < 4; j++) {
            int n = bn + tx * 4 + j;
            if (n >= N) continue;
            float x = acc[i2][j] + bias[n];
            if (ACT == 0) x = fmaxf(x, 0.f);
            else          x = 1.f / (1.f + __expf(-x));
            C[(size_t)m * N + n] = x;
        }
    }
}

// ---------------- launch ----------------
extern "C" void kernel_launch(void* const* d_in, const int* in_sizes, int n_in,
                              void* d_out, int out_size)
{
    const int*   ei  = (const int*)d_in[0];
    const float* ue  = (const float*)d_in[1];
    const float* it  = (const float*)d_in[2];
    const float* cw1 = (const float*)d_in[3];  const float* cb1 = (const float*)d_in[4];
    const float* cw2 = (const float*)d_in[5];  const float* cb2 = (const float*)d_in[6];
    const float* aw1 = (const float*)d_in[7];  const float* ab1 = (const float*)d_in[8];
    const float* aw2 = (const float*)d_in[9];  const float* ab2 = (const float*)d_in[10];
    const float* sw1 = (const float*)d_in[11]; const float* sb1 = (const float*)d_in[12];
    const float* sw2 = (const float*)d_in[13]; const float* sb2 = (const float*)d_in[14];

    float* out     = (float*)d_out;
    float* o_churn = out;                                         // [U, 1]
    float* o_cat   = o_churn + (size_t)NUM_USERS;                 // [U, 100]
    float* o_sku   = o_cat   + (size_t)NUM_USERS * NUM_CAT;       // [U, 2000]
    float* o_u     = o_sku   + (size_t)NUM_USERS * NUM_SKU;       // [U, 128]

    float* hbuf = nullptr;
    cudaGetSymbolAddress((void**)&hbuf, g_h);

    const int nb = (N_NODES + T_SCAN - 1) / T_SCAN;   // 147

    // graph build
    k_zero<<<(N_NODES + 255) / 256, 256>>>();
    k_deg<<<(N_EDGES + 255) / 256, 256>>>(ei);
    k_scan_part<<<nb, T_SCAN>>>();
    k_scan_base<<<1, 32>>>(nb);
    k_scan_add<<<nb, T_SCAN>>>();
    k_fill<<<(N_EDGES + 255) / 256, 256>>>(ei);

    // propagation (3 layers, ping-pong; last layer: user rows only)
    k_embinit<<<((size_t)N_NODES * EMBED + 255) / 256, 256>>>(ue, it);
    k_prop<<<N_NODES, 128>>>(0);     // emb0 -> emb1
    k_prop<<<N_NODES, 128>>>(1);     // emb1 -> emb0
    k_prop<<<NUM_USERS, 128>>>(0);   // emb0 -> emb1 (only user rows needed)
    k_u<<<((size_t)NUM_USERS * EMBED + 255) / 256, 256>>>(o_u);

    // MLP heads
    dim3 blk(256);
    dim3 gH((HID + 63) / 64, (NUM_USERS + 63) / 64);
    // churn
    k_gemm<0><<<gH, blk>>>(o_u, cw1, cb1, hbuf, NUM_USERS, HID);
    k_gemm<1><<<dim3(1, (NUM_USERS + 63) / 64), blk>>>(hbuf, cw2, cb2, o_churn, NUM_USERS, 1);
    // cat
    k_gemm<0><<<gH, blk>>>(o_u, aw1, ab1, hbuf, NUM_USERS, HID);
    k_gemm<1><<<dim3((NUM_CAT + 63) / 64, (NUM_USERS + 63) / 64), blk>>>(hbuf, aw2, ab2, o_cat, NUM_USERS, NUM_CAT);
    // sku
    k_gemm<0><<<gH, blk>>>(o_u, sw1, sb1, hbuf, NUM_USERS, HID);
    k_gemm<1><<<dim3((NUM_SKU + 63) / 64, (NUM_USERS + 63) / 64), blk>>>(hbuf, sw2, sb2, o_sku, NUM_USERS, NUM_SKU);
}

// round 3
// speedup vs baseline: 2.1561x; 2.1561x over previous
#include <cuda_runtime.h>
#include <cuda_bf16.h>
#include <math.h>
#include <stdint.h>

#define NUM_USERS 100000
#define NUM_ITEMS 50000
#define N_NODES   150000
#define EMBED     128
#define N_EDGES   1000000
#define N_SYM     (2*N_EDGES)
#define HID       128
#define NUM_CAT   100
#define NUM_SKU   2000

// ---------------- static device scratch ----------------
__device__ int   g_deg[N_NODES];
__device__ int   g_off[N_NODES + 1];
__device__ int   g_cur[N_NODES];
__device__ int   g_adj_col[N_SYM];
__device__ float g_adj_w[N_SYM];
__device__ float g_emb0[(size_t)N_NODES * EMBED];
__device__ float g_emb1[(size_t)N_NODES * EMBED];
__device__ float g_acc[(size_t)NUM_USERS * EMBED];
__device__ int   g_bsum[256];
// bf16 split operand buffers
__device__ __nv_bfloat16 g_Uhi[(size_t)NUM_USERS * EMBED];
__device__ __nv_bfloat16 g_Ulo[(size_t)NUM_USERS * EMBED];
__device__ __nv_bfloat16 g_Hhi[(size_t)NUM_USERS * HID];
__device__ __nv_bfloat16 g_Hlo[(size_t)NUM_USERS * HID];
__device__ __nv_bfloat16 g_Bthi[2048 * 128];   // transposed weights [n][k]
__device__ __nv_bfloat16 g_Btlo[2048 * 128];

#define T_SCAN 1024

// ================= warp-MMA helpers (baseline PTX, no 'a' features) =================
__device__ __forceinline__ uint32_t smem_u32(const void* p) {
    uint32_t a;
    asm("{ .reg .u64 t; cvta.to.shared.u64 t, %1; cvt.u32.u64 %0, t; }" : "=r"(a) : "l"(p));
    return a;
}
__device__ __forceinline__ void ldsm_x4(uint32_t r[4], uint32_t addr) {
    asm volatile("ldmatrix.sync.aligned.m8n8.x4.shared.b16 {%0,%1,%2,%3}, [%4];"
                 : "=r"(r[0]), "=r"(r[1]), "=r"(r[2]), "=r"(r[3]) : "r"(addr));
}
__device__ __forceinline__ void ldsm_x2(uint32_t r[2], uint32_t addr) {
    asm volatile("ldmatrix.sync.aligned.m8n8.x2.shared.b16 {%0,%1}, [%2];"
                 : "=r"(r[0]), "=r"(r[1]) : "r"(addr));
}
__device__ __forceinline__ void mma_bf16(float c[4], const uint32_t a[4], const uint32_t b[2]) {
    asm volatile("mma.sync.aligned.m16n8k16.row.col.f32.bf16.bf16.f32 "
                 "{%0,%1,%2,%3}, {%4,%5,%6,%7}, {%8,%9}, {%0,%1,%2,%3};"
                 : "+f"(c[0]), "+f"(c[1]), "+f"(c[2]), "+f"(c[3])
                 : "r"(a[0]), "r"(a[1]), "r"(a[2]), "r"(a[3]), "r"(b[0]), "r"(b[1]));
}

// ---------------- graph build ----------------
__global__ void k_zero() {
    int i = blockIdx.x * blockDim.x + threadIdx.x;
    if (i < N_NODES) { g_deg[i] = 0; g_cur[i] = 0; }
}
__global__ void k_deg(const int* __restrict__ ei) {
    int e = blockIdx.x * blockDim.x + threadIdx.x;
    if (e < N_EDGES) {
        atomicAdd(&g_deg[ei[e]], 1);
        atomicAdd(&g_deg[ei[N_EDGES + e]], 1);
    }
}
__global__ void k_scan_part() {
    __shared__ int s[T_SCAN];
    int t = threadIdx.x, b = blockIdx.x;
    int i = b * T_SCAN + t;
    int v = (i < N_NODES) ? g_deg[i] : 0;
    s[t] = v;
    __syncthreads();
    for (int d = 1; d < T_SCAN; d <<= 1) {
        int x = (t >= d) ? s[t - d] : 0;
        __syncthreads();
        s[t] += x;
        __syncthreads();
    }
    if (i < N_NODES) g_off[i] = s[t] - v;
    if (t == T_SCAN - 1) g_bsum[b] = s[t];
}
__global__ void k_scan_base(int nb) {
    if (threadIdx.x == 0 && blockIdx.x == 0) {
        int run = 0;
        for (int b = 0; b < nb; b++) { int x = g_bsum[b]; g_bsum[b] = run; run += x; }
        g_off[N_NODES] = run;
    }
}
__global__ void k_scan_add() {
    int i = blockIdx.x * T_SCAN + threadIdx.x;
    if (i < N_NODES) g_off[i] += g_bsum[blockIdx.x];
}
__global__ void k_fill(const int* __restrict__ ei) {
    int e = blockIdx.x * blockDim.x + threadIdx.x;
    if (e >= N_EDGES) return;
    int r = ei[e];
    int c = ei[N_EDGES + e];
    float nrm = rsqrtf((float)g_deg[r]) * rsqrtf((float)g_deg[c]);
    int p = atomicAdd(&g_cur[r], 1);
    g_adj_col[g_off[r] + p] = c; g_adj_w[g_off[r] + p] = nrm;
    int q = atomicAdd(&g_cur[c], 1);
    g_adj_col[g_off[c] + q] = r; g_adj_w[g_off[c] + q] = nrm;
}
__global__ void k_embinit(const float* __restrict__ ue, const float* __restrict__ it) {
    size_t i = (size_t)blockIdx.x * blockDim.x + threadIdx.x;
    const size_t nu  = (size_t)NUM_USERS * EMBED;
    const size_t tot = (size_t)N_NODES * EMBED;
    if (i >= tot) return;
    float v = (i < nu) ? ue[i] : it[i - nu];
    g_emb0[i] = v;
    if (i < nu) g_acc[i] = v;
}

// ---------------- propagation: one warp per row, float4 lanes ----------------
__global__ void k_prop4(int sel, int nrows) {
    const float4* __restrict__ src = (const float4*)(sel ? g_emb1 : g_emb0);
    float*        dstf             = sel ? g_emb0 : g_emb1;
    int warp = (blockIdx.x * blockDim.x + threadIdx.x) >> 5;
    int lane = threadIdx.x & 31;
    if (warp >= nrows) return;
    int s = g_off[warp], e2 = g_off[warp + 1];
    float4 a = make_float4(0.f, 0.f, 0.f, 0.f);
    int e = s;
    for (; e + 4 <= e2; e += 4) {
        int   c0 = g_adj_col[e],   c1 = g_adj_col[e+1], c2 = g_adj_col[e+2], c3 = g_adj_col[e+3];
        float w0 = g_adj_w[e],     w1 = g_adj_w[e+1],   w2 = g_adj_w[e+2],   w3 = g_adj_w[e+3];
        float4 v0 = src[c0 * 32 + lane];
        float4 v1 = src[c1 * 32 + lane];
        float4 v2 = src[c2 * 32 + lane];
        float4 v3 = src[c3 * 32 + lane];
        a.x = fmaf(w0, v0.x, a.x); a.y = fmaf(w0, v0.y, a.y); a.z = fmaf(w0, v0.z, a.z); a.w = fmaf(w0, v0.w, a.w);
        a.x = fmaf(w1, v1.x, a.x); a.y = fmaf(w1, v1.y, a.y); a.z = fmaf(w1, v1.z, a.z); a.w = fmaf(w1, v1.w, a.w);
        a.x = fmaf(w2, v2.x, a.x); a.y = fmaf(w2, v2.y, a.y); a.z = fmaf(w2, v2.z, a.z); a.w = fmaf(w2, v2.w, a.w);
        a.x = fmaf(w3, v3.x, a.x); a.y = fmaf(w3, v3.y, a.y); a.z = fmaf(w3, v3.z, a.z); a.w = fmaf(w3, v3.w, a.w);
    }
    for (; e < e2; e++) {
        int c = g_adj_col[e]; float w = g_adj_w[e];
        float4 v = src[c * 32 + lane];
        a.x = fmaf(w, v.x, a.x); a.y = fmaf(w, v.y, a.y); a.z = fmaf(w, v.z, a.z); a.w = fmaf(w, v.w, a.w);
    }
    ((float4*)(dstf + (size_t)warp * EMBED))[lane] = a;
    if (warp < NUM_USERS) {
        float4* ac = (float4*)(g_acc + (size_t)warp * EMBED);
        float4 t = ac[lane];
        t.x += a.x; t.y += a.y; t.z += a.z; t.w += a.w;
        ac[lane] = t;
    }
}

// final user embedding + bf16 hi/lo split of u
__global__ void k_u(float* __restrict__ uo) {
    size_t i = (size_t)blockIdx.x * blockDim.x + threadIdx.x;
    if (i >= (size_t)NUM_USERS * EMBED) return;
    float v = g_acc[i] * 0.25f;
    uo[i] = v;
    __nv_bfloat16 h = __float2bfloat16(v);
    g_Uhi[i] = h;
    g_Ulo[i] = __float2bfloat16(v - __bfloat162float(h));
}

// churn layer-2: sigmoid(h @ w2 + b), N=1. One warp per row (h = hi + lo planes).
__global__ void k_churn2(const float* __restrict__ w2, const float* __restrict__ b2,
                         float* __restrict__ out) {
    int warp = (blockIdx.x * blockDim.x + threadIdx.x) >> 5;
    int lane = threadIdx.x & 31;
    if (warp >= NUM_USERS) return;
    const __nv_bfloat162* hh = (const __nv_bfloat162*)(g_Hhi + (size_t)warp * HID);
    const __nv_bfloat162* hl = (const __nv_bfloat162*)(g_Hlo + (size_t)warp * HID);
    const float2* w = (const float2*)w2;
    float s = 0.f;
    #pragma unroll
    for (int t = 0; t < 2; t++) {
        int idx = lane + t * 32;
        __nv_bfloat162 a2 = hh[idx], b2v = hl[idx];
        float2 wv = w[idx];
        float h0 = __bfloat162float(a2.x) + __bfloat162float(b2v.x);
        float h1 = __bfloat162float(a2.y) + __bfloat162float(b2v.y);
        s = fmaf(h0, wv.x, s);
        s = fmaf(h1, wv.y, s);
    }
    #pragma unroll
    for (int o = 16; o > 0; o >>= 1) s += __shfl_xor_sync(0xFFFFFFFF, s, o);
    if (lane == 0) out[warp] = 1.f / (1.f + __expf(-(s + b2[0])));
}

// weights: B [K=128, N] row-major -> transposed bf16 hi/lo [n][k]
__global__ void k_prepB(const float* __restrict__ B, int N) {
    int i = blockIdx.x * blockDim.x + threadIdx.x;
    if (i >= N * 128) return;
    int n = i >> 7, k = i & 127;
    float v = B[(size_t)k * N + n];
    __nv_bfloat16 h = __float2bfloat16(v);
    g_Bthi[n * 128 + k] = h;
    g_Btlo[n * 128 + k] = __float2bfloat16(v - __bfloat162float(h));
}

// ---------------- warp-MMA bf16-split GEMM ----------------
// C[M,N] = act(A[M,128] @ B[128,N] + bias), A given as hi/lo bf16 (pitch 128),
// B given as g_Bthi/g_Btlo transposed [n][k].
// CTA tile 128x128, K-loop of 64, 8 warps (2x4), warp tile 64x32.
// MODE 0: write fp32 C.  MODE 1: write bf16 hi/lo planes (pitch 128).
// ACT  0: relu.          ACT  1: sigmoid.
#define SA_HI 0
#define SA_LO 16384
#define SB_HI 32768
#define SB_LO 49152
#define OPITCH 132
#define SMEM_MMA (128 * OPITCH * 4)   // 67584 >= 65536 tile area

template <int ACT, int MODE>
__global__ void __launch_bounds__(256, 2) k_tmma(
    const __nv_bfloat16* __restrict__ Ahi, const __nv_bfloat16* __restrict__ Alo,
    const float* __restrict__ bias, float* __restrict__ C,
    __nv_bfloat16* __restrict__ Phi, __nv_bfloat16* __restrict__ Plo,
    int M, int N)
{
    extern __shared__ char sm[];
    const uint32_t sb = smem_u32(sm);
    const int tid  = threadIdx.x;
    const int wid  = tid >> 5;
    const int lane = tid & 31;
    const int bm = blockIdx.y * 128;
    const int bn = blockIdx.x * 128;
    const int wm = (wid >> 2) * 64;     // warp m offset (0/64)
    const int wn = (wid & 3) * 32;      // warp n offset (0/32/64/96)

    float acc[4][4][4];
    #pragma unroll
    for (int i = 0; i < 4; i++)
        #pragma unroll
        for (int j = 0; j < 4; j++)
            #pragma unroll
            for (int t = 0; t < 4; t++) acc[i][j][t] = 0.f;

    for (int kt = 0; kt < 128; kt += 64) {
        // --- stage tiles: 4 planes x 128 rows x 8 chunks(16B), XOR-swizzled ---
        #pragma unroll
        for (int it = 0; it < 4; it++) {
            int idx = tid + it * 256;           // 0..1023
            int r = idx >> 3, c = idx & 7;
            uint32_t dst = (uint32_t)(r * 128 + ((c ^ (r & 7)) << 4));
            uint4 z = make_uint4(0, 0, 0, 0);
            // A hi / lo
            uint4 vh = z, vl = z;
            int gr = bm + r;
            if (gr < M) {
                vh = *(const uint4*)(Ahi + (size_t)gr * 128 + kt + c * 8);
                vl = *(const uint4*)(Alo + (size_t)gr * 128 + kt + c * 8);
            }
            *(uint4*)(sm + SA_HI + dst) = vh;
            *(uint4*)(sm + SA_LO + dst) = vl;
            // B hi / lo
            uint4 wh = z, wl = z;
            int gn = bn + r;
            if (gn < N) {
                wh = *(const uint4*)(g_Bthi + (size_t)gn * 128 + kt + c * 8);
                wl = *(const uint4*)(g_Btlo + (size_t)gn * 128 + kt + c * 8);
            }
            *(uint4*)(sm + SB_HI + dst) = wh;
            *(uint4*)(sm + SB_LO + dst) = wl;
        }
        __syncthreads();

        #pragma unroll
        for (int ks = 0; ks < 4; ks++) {
            const int k0 = ks * 16;
            // B fragments for 4 n-frags (hi & lo)
            uint32_t bh[4][2], bl[4][2];
            {
                const int n_l = wn + (lane & 7);
                const int k_l = k0 + ((lane & 8) ? 8 : 0);
                const uint32_t swz = (uint32_t)((((k_l >> 3) ^ (n_l & 7)) << 4) + n_l * 128 + (k_l & 7) * 0);
                #pragma unroll
                for (int j = 0; j < 4; j++) {
                    uint32_t off = (uint32_t)((n_l + j * 8) * 128 + (((k_l >> 3) ^ ((n_l + j * 8) & 7)) << 4));
                    ldsm_x2(bh[j], sb + SB_HI + off);
                    ldsm_x2(bl[j], sb + SB_LO + off);
                }
                (void)swz;
            }
            // per m-frag: load A hi/lo, 12 MMAs
            #pragma unroll
            for (int mi = 0; mi < 4; mi++) {
                const int m_l = wm + mi * 16 + (lane & 7) + (lane & 8);
                const int k_l = k0 + ((lane & 16) ? 8 : 0);
                const uint32_t off = (uint32_t)(m_l * 128 + (((k_l >> 3) ^ (m_l & 7)) << 4));
                uint32_t ah[4], al[4];
                ldsm_x4(ah, sb + SA_HI + off);
                ldsm_x4(al, sb + SA_LO + off);
                #pragma unroll
                for (int j = 0; j < 4; j++) {
                    mma_bf16(acc[mi][j], ah, bh[j]);
                    mma_bf16(acc[mi][j], al, bh[j]);
                    mma_bf16(acc[mi][j], ah, bl[j]);
                }
            }
        }
        __syncthreads();
    }

    // --- epilogue: bias + act -> smem staging -> coalesced stores ---
    float* outS = (float*)sm;
    #pragma unroll
    for (int mi = 0; mi < 4; mi++) {
        const int r0 = wm + mi * 16 + (lane >> 2);
        #pragma unroll
        for (int j = 0; j < 4; j++) {
            const int c0 = wn + j * 8 + 2 * (lane & 3);
            float b0 = (bn + c0     < N) ? __ldg(&bias[bn + c0])     : 0.f;
            float b1 = (bn + c0 + 1 < N) ? __ldg(&bias[bn + c0 + 1]) : 0.f;
            #pragma unroll
            for (int h = 0; h < 2; h++) {            // h=0: rows r0, h=1: rows r0+8
                float x0 = acc[mi][j][2 * h + 0] + b0;
                float x1 = acc[mi][j][2 * h + 1] + b1;
                if (ACT == 0) { x0 = fmaxf(x0, 0.f); x1 = fmaxf(x1, 0.f); }
                else { x0 = 1.f / (1.f + __expf(-x0)); x1 = 1.f / (1.f + __expf(-x1)); }
                outS[(r0 + 8 * h) * OPITCH + c0]     = x0;
                outS[(r0 + 8 * h) * OPITCH + c0 + 1] = x1;
            }
        }
    }
    __syncthreads();

    // coalesced write-out: 128 rows x 32 float4
    for (int idx = tid; idx < 128 * 32; idx += 256) {
        int r = idx >> 5;
        int col = (idx & 31) * 4;
        int m = bm + r;
        if (m >= M || bn + col >= N) continue;
        float4 v = *(float4*)&outS[r * OPITCH + col];
        if (MODE == 0) {
            *(float4*)&C[(size_t)m * N + bn + col] = v;
        } else {
            __nv_bfloat16 h0 = __float2bfloat16(v.x);
            __nv_bfloat16 h1 = __float2bfloat16(v.y);
            __nv_bfloat16 h2 = __float2bfloat16(v.z);
            __nv_bfloat16 h3 = __float2bfloat16(v.w);
            __nv_bfloat16 l0 = __float2bfloat16(v.x - __bfloat162float(h0));
            __nv_bfloat16 l1 = __float2bfloat16(v.y - __bfloat162float(h1));
            __nv_bfloat16 l2 = __float2bfloat16(v.z - __bfloat162float(h2));
            __nv_bfloat16 l3 = __float2bfloat16(v.w - __bfloat162float(h3));
            __nv_bfloat162 hp0 = {h0, h1}, hp1 = {h2, h3};
            __nv_bfloat162 lp0 = {l0, l1}, lp1 = {l2, l3};
            uint2 hv, lv;
            hv.x = *(uint32_t*)&hp0; hv.y = *(uint32_t*)&hp1;
            lv.x = *(uint32_t*)&lp0; lv.y = *(uint32_t*)&lp1;
            *(uint2*)&Phi[(size_t)m * 128 + bn + col] = hv;
            *(uint2*)&Plo[(size_t)m * 128 + bn + col] = lv;
        }
    }
}

// ---------------- launch ----------------
extern "C" void kernel_launch(void* const* d_in, const int* in_sizes, int n_in,
                              void* d_out, int out_size)
{
    const int*   ei  = (const int*)d_in[0];
    const float* ue  = (const float*)d_in[1];
    const float* it  = (const float*)d_in[2];
    const float* cw1 = (const float*)d_in[3];  const float* cb1 = (const float*)d_in[4];
    const float* cw2 = (const float*)d_in[5];  const float* cb2 = (const float*)d_in[6];
    const float* aw1 = (const float*)d_in[7];  const float* ab1 = (const float*)d_in[8];
    const float* aw2 = (const float*)d_in[9];  const float* ab2 = (const float*)d_in[10];
    const float* sw1 = (const float*)d_in[11]; const float* sb1 = (const float*)d_in[12];
    const float* sw2 = (const float*)d_in[13]; const float* sb2 = (const float*)d_in[14];

    float* out     = (float*)d_out;
    float* o_churn = out;
    float* o_cat   = o_churn + (size_t)NUM_USERS;
    float* o_sku   = o_cat   + (size_t)NUM_USERS * NUM_CAT;
    float* o_u     = o_sku   + (size_t)NUM_USERS * NUM_SKU;

    __nv_bfloat16 *uhi = nullptr, *ulo = nullptr, *hhi = nullptr, *hlo = nullptr;
    cudaGetSymbolAddress((void**)&uhi, g_Uhi);
    cudaGetSymbolAddress((void**)&ulo, g_Ulo);
    cudaGetSymbolAddress((void**)&hhi, g_Hhi);
    cudaGetSymbolAddress((void**)&hlo, g_Hlo);

    cudaFuncSetAttribute(k_tmma<0, 1>, cudaFuncAttributeMaxDynamicSharedMemorySize, SMEM_MMA);
    cudaFuncSetAttribute(k_tmma<1, 0>, cudaFuncAttributeMaxDynamicSharedMemorySize, SMEM_MMA);

    const int nb = (N_NODES + T_SCAN - 1) / T_SCAN;

    // graph build
    k_zero<<<(N_NODES + 255) / 256, 256>>>();
    k_deg<<<(N_EDGES + 255) / 256, 256>>>(ei);
    k_scan_part<<<nb, T_SCAN>>>();
    k_scan_base<<<1, 32>>>(nb);
    k_scan_add<<<nb, T_SCAN>>>();
    k_fill<<<(N_EDGES + 255) / 256, 256>>>(ei);

    // propagation
    k_embinit<<<((size_t)N_NODES * EMBED + 255) / 256, 256>>>(ue, it);
    k_prop4<<<(N_NODES   + 7) / 8, 256>>>(0, N_NODES);
    k_prop4<<<(N_NODES   + 7) / 8, 256>>>(1, N_NODES);
    k_prop4<<<(NUM_USERS + 7) / 8, 256>>>(0, NUM_USERS);
    k_u<<<((size_t)NUM_USERS * EMBED + 255) / 256, 256>>>(o_u);

    const int MT = (NUM_USERS + 127) / 128;      // 782
    dim3 blk(256);

    // churn: tensor layer-1 (-> hi/lo planes) + warp-dot layer-2
    k_prepB<<<(HID * 128 + 255) / 256, 256>>>(cw1, HID);
    k_tmma<0, 1><<<dim3(1, MT), blk, SMEM_MMA>>>(uhi, ulo, cb1, nullptr, hhi, hlo, NUM_USERS, HID);
    k_churn2<<<(NUM_USERS * 32 + 255) / 256, 256>>>(cw2, cb2, o_churn);

    // cat
    k_prepB<<<(HID * 128 + 255) / 256, 256>>>(aw1, HID);
    k_tmma<0, 1><<<dim3(1, MT), blk, SMEM_MMA>>>(uhi, ulo, ab1, nullptr, hhi, hlo, NUM_USERS, HID);
    k_prepB<<<(NUM_CAT * 128 + 255) / 256, 256>>>(aw2, NUM_CAT);
    k_tmma<1, 0><<<dim3(1, MT), blk, SMEM_MMA>>>(hhi, hlo, ab2, o_cat, nullptr, nullptr, NUM_USERS, NUM_CAT);

    // sku
    k_prepB<<<(HID * 128 + 255) / 256, 256>>>(sw1, HID);
    k_tmma<0, 1><<<dim3(1, MT), blk, SMEM_MMA>>>(uhi, ulo, sb1, nullptr, hhi, hlo, NUM_USERS, HID);
    k_prepB<<<(NUM_SKU * 128 + 255) / 256, 256>>>(sw2, NUM_SKU);
    k_tmma<1, 0><<<dim3((NUM_SKU + 127) / 128, MT), blk, SMEM_MMA>>>(hhi, hlo, sb2, o_sku, nullptr, nullptr, NUM_USERS, NUM_SKU);
}